// round 8
// baseline (speedup 1.0000x reference)
#include <cuda_runtime.h>
#include <cuda_bf16.h>
#include <math.h>
#include <stdint.h>

// Problem constants (fixed by the dataset)
#define D_DIM   1024
#define F_DIM   2048
#define E_NUM   8
#define N_TOK   2048
#define NPAIR   4096
#define PADROWS 5120
#define MAXTILES 40
#define NS1 32            // 1024/32 K-stages, GEMM1
#define NS2 64            // 2048/32 K-stages, GEMM2
#define LDA 36            // fp32 elems per row (32 + 4 pad) -> 144B stride

#define A_BYTES  (128 * LDA * 4)          // 18432
#define B_BYTES  (64 * LDA * 4)           // 9216
#define STAGE1   (A_BYTES + 2 * B_BYTES)  // 36864
#define STAGE2   (A_BYTES + B_BYTES)      // 27648
#define SMEM1    (2 * STAGE1)             // 73728
#define SMEM2    (2 * STAGE2)             // 55296

// Scratch (device globals — no runtime allocation allowed)
__device__ float g_inner[(size_t)PADROWS * F_DIM];   // tf32-rounded fp32
__device__ int   g_pair_token[PADROWS];
__device__ float g_pair_w[PADROWS];
__device__ int   g_topi[N_TOK * 2];
__device__ float g_topw[N_TOK * 2];
__device__ int   g_counts[E_NUM];
__device__ int   g_cursor[E_NUM];
__device__ int   g_tile_e[MAXTILES];

__device__ __forceinline__ uint32_t f2tf(float f) {
    uint32_t u;
    asm("cvt.rna.tf32.f32 %0, %1;" : "=r"(u) : "f"(f));
    return u;
}
__device__ __forceinline__ uint32_t s2u(const void* p) {
    return (uint32_t)__cvta_generic_to_shared((void*)p);
}
__device__ __forceinline__ void mma_tf32(float c[4], const uint32_t a[4],
                                         const uint32_t b[2]) {
    asm volatile(
        "mma.sync.aligned.m16n8k8.row.col.f32.tf32.tf32.f32 "
        "{%0,%1,%2,%3}, {%4,%5,%6,%7}, {%8,%9}, {%0,%1,%2,%3};\n"
        : "+f"(c[0]), "+f"(c[1]), "+f"(c[2]), "+f"(c[3])
        : "r"(a[0]), "r"(a[1]), "r"(a[2]), "r"(a[3]), "r"(b[0]), "r"(b[1]));
}
__device__ __forceinline__ void ldsm4(uint32_t r[4], uint32_t addr) {
    asm volatile("ldmatrix.sync.aligned.m8n8.x4.shared.b16 {%0,%1,%2,%3}, [%4];"
                 : "=r"(r[0]), "=r"(r[1]), "=r"(r[2]), "=r"(r[3]) : "r"(addr));
}
// ldsm4 with our aoff returns {(r0-7,k0-3),(r0-7,k4-7),(r8-15,k0-3),(r8-15,k4-7)}.
// The tf32 A fragment wants {a0,a1,a2,a3}={(g4,t4),(g4+8,t4),(g4,t4+4),(g4+8,t4+4)}
// = {r0, r2, r1, r3}  -> reorder here.
__device__ __forceinline__ void ldsmA(uint32_t a[4], uint32_t addr) {
    uint32_t r[4];
    ldsm4(r, addr);
    a[0] = r[0]; a[1] = r[2]; a[2] = r[1]; a[3] = r[3];
}

// ---------------------------------------------------------------------------
// small kernels
// ---------------------------------------------------------------------------
__global__ void init_kernel(float* out, int out_size) {
    int idx = blockIdx.x * blockDim.x + threadIdx.x;
    if (idx < out_size) out[idx] = 0.f;
    if (idx < PADROWS)  g_pair_token[idx] = -1;
    if (idx < E_NUM)    g_counts[idx] = 0;
}

__global__ void router_kernel(const float* __restrict__ x,
                              const float* __restrict__ Wg) {
    int warp = threadIdx.x >> 5;
    int lane = threadIdx.x & 31;
    int n = blockIdx.x * 8 + warp;
    if (n >= N_TOK) return;
    float acc[E_NUM];
#pragma unroll
    for (int e = 0; e < E_NUM; e++) acc[e] = 0.f;
    const float* xr = x + (size_t)n * D_DIM;
    for (int d = lane; d < D_DIM; d += 32) {
        float xv = xr[d];
#pragma unroll
        for (int e = 0; e < E_NUM; e++) acc[e] += xv * Wg[d * E_NUM + e];
    }
#pragma unroll
    for (int e = 0; e < E_NUM; e++) {
#pragma unroll
        for (int off = 16; off > 0; off >>= 1)
            acc[e] += __shfl_xor_sync(0xffffffffu, acc[e], off);
    }
    if (lane == 0) {
        float m = acc[0];
#pragma unroll
        for (int e = 1; e < E_NUM; e++) m = fmaxf(m, acc[e]);
        float p[E_NUM];
#pragma unroll
        for (int e = 0; e < E_NUM; e++) p[e] = expf(acc[e] - m);
        int i1 = 0;
#pragma unroll
        for (int e = 1; e < E_NUM; e++) if (p[e] > p[i1]) i1 = e;
        int i2 = (i1 == 0) ? 1 : 0;
#pragma unroll
        for (int e = 0; e < E_NUM; e++)
            if (e != i1 && p[e] > p[i2]) i2 = e;
        float inv = 1.f / (p[i1] + p[i2]);
        g_topi[n * 2 + 0] = i1;  g_topw[n * 2 + 0] = p[i1] * inv;
        g_topi[n * 2 + 1] = i2;  g_topw[n * 2 + 1] = p[i2] * inv;
        atomicAdd(&g_counts[i1], 1);
        atomicAdd(&g_counts[i2], 1);
    }
}

__global__ void setup_kernel() {
    if (threadIdx.x != 0 || blockIdx.x != 0) return;
    int off = 0;
    int pad[E_NUM];
    for (int e = 0; e < E_NUM; e++) {
        g_cursor[e] = off;
        int p = ((g_counts[e] + 127) / 128) * 128;
        pad[e] = p;
        off += p;
    }
    int t = 0;
    for (int e = 0; e < E_NUM; e++)
        for (int r = 0; r < pad[e]; r += 128) g_tile_e[t++] = e;
    for (; t < MAXTILES; t++) g_tile_e[t] = -1;
}

__global__ void scatter_kernel() {
    int idx = blockIdx.x * blockDim.x + threadIdx.x;
    if (idx >= NPAIR) return;
    int e = g_topi[idx];
    int pos = atomicAdd(&g_cursor[e], 1);
    g_pair_token[pos] = idx >> 1;
    g_pair_w[pos] = g_topw[idx];
}

// ---------------------------------------------------------------------------
// B-tile store: cvt.rna + 4x4 shfl transpose + STS.128 (conflict-free).
// Lane (a = lane>>2, b = lane&3) loaded bv[p] = W[khb+4p+b][n cols nh+a*4..+3].
// After transpose lane holds n = nh + a*4 + b, k-run of 4 at khb+4p.
// ---------------------------------------------------------------------------
__device__ __forceinline__ void sts_B(char* sB, const float4* bv, int np,
                                      int nh, int khb, int lane) {
    int a = lane >> 2, b = lane & 3;
#pragma unroll
    for (int p = 0; p < 4; p++) {
        if (p >= np) break;
        uint32_t t[4] = { f2tf(bv[p].x), f2tf(bv[p].y), f2tf(bv[p].z), f2tf(bv[p].w) };
        uint32_t w4[4];
#pragma unroll
        for (int s = 0; s < 4; s++) {
            int j = (b - s) & 3;
            w4[j] = __shfl_sync(0xffffffffu, t[(b + s) & 3], (lane & ~3) | j);
        }
        int n = nh + a * 4 + b;
        *(uint4*)(sB + n * (LDA * 4) + (khb + p * 4) * 4) =
            make_uint4(w4[0], w4[1], w4[2], w4[3]);
    }
}

// ---------------------------------------------------------------------------
// GEMM1: inner = gelu(X@W_in + b_in) * (X@W_scale + b_scale)
// Grid (F/64, MAXTILES). 256 thr, warps: wm=warp&3 (32 rows), wn=warp>>2 (32 cols).
// ---------------------------------------------------------------------------
extern __shared__ __align__(16) char dynsmem[];

__global__ __launch_bounds__(256, 1)
void gemm1_kernel(const float* __restrict__ x,   const float* __restrict__ Win,
                  const float* __restrict__ bin, const float* __restrict__ Wsc,
                  const float* __restrict__ bsc) {
    int e = g_tile_e[blockIdx.y];
    if (e < 0) return;
    int row0 = blockIdx.y * 128;
    int n0   = blockIdx.x * 64;

    int tid = threadIdx.x;
    int lane = tid & 31, warp = tid >> 5;
    int wm = warp & 3, wn = warp >> 2;
    int g4 = lane >> 2, t4 = lane & 3;

    // A gather mapping: rows rA + 32i, fixed kv
    int rA = tid >> 3, kv = tid & 7;
    const float* xptr[4];
    bool tval[4];
#pragma unroll
    for (int i = 0; i < 4; i++) {
        int tok = g_pair_token[row0 + rA + i * 32];
        tval[i] = (tok >= 0);
        xptr[i] = x + (size_t)(tok >= 0 ? tok : 0) * D_DIM + kv * 4;
    }
    // B loader mapping: warp -> matrix (warp&1), k-half khB, n-half nhB
    int aq = lane >> 2, bq = lane & 3;
    int khB = ((warp >> 1) & 1) * 16;
    int nhB = (warp >> 2) * 32;
    const float* wsel = (warp & 1) ? Wsc : Win;
    const float* bbase = wsel + ((size_t)e * D_DIM + khB + bq) * F_DIM + n0 + nhB + aq * 4;

    // ldmatrix per-lane offset: lanes 0-7 rows 0-7 k0-3; 8-15 rows 0-7 k4-7;
    // 16-23 rows 8-15 k0-3; 24-31 rows 8-15 k4-7.
    uint32_t aoff = (uint32_t)(((lane & 7) + ((lane >> 4) & 1) * 8) * (LDA * 4)
                               + ((lane >> 3) & 1) * 16);

    float cH[2][4][4], cS[2][4][4];
#pragma unroll
    for (int mi = 0; mi < 2; mi++)
#pragma unroll
        for (int ni = 0; ni < 4; ni++)
#pragma unroll
            for (int j = 0; j < 4; j++) { cH[mi][ni][j] = 0.f; cS[mi][ni][j] = 0.f; }

    float4 av[4], bv[4];
    // prologue loads for k0 = 0
#pragma unroll
    for (int i = 0; i < 4; i++)
        av[i] = tval[i] ? *(const float4*)(xptr[i]) : make_float4(0.f, 0.f, 0.f, 0.f);
#pragma unroll
    for (int p = 0; p < 4; p++)
        bv[p] = *(const float4*)(bbase + (size_t)(p * 4) * F_DIM);

    for (int it = 0; it < NS1; it++) {
        char* sA  = dynsmem + (it & 1) * STAGE1;
        char* sB1 = sA + A_BYTES;
        char* sB2 = sB1 + B_BYTES;
        // store current stage
#pragma unroll
        for (int i = 0; i < 4; i++) {
            uint4 u = make_uint4(f2tf(av[i].x), f2tf(av[i].y), f2tf(av[i].z), f2tf(av[i].w));
            *(uint4*)(sA + (rA + i * 32) * (LDA * 4) + kv * 16) = u;
        }
        sts_B((warp & 1) ? sB2 : sB1, bv, 4, nhB, khB, lane);
        __syncthreads();
        // prefetch next stage
        if (it + 1 < NS1) {
            int k0 = (it + 1) * 32;
#pragma unroll
            for (int i = 0; i < 4; i++)
                av[i] = tval[i] ? *(const float4*)(xptr[i] + k0)
                                : make_float4(0.f, 0.f, 0.f, 0.f);
#pragma unroll
            for (int p = 0; p < 4; p++)
                bv[p] = *(const float4*)(bbase + (size_t)(k0 + p * 4) * F_DIM);
        }
        // compute
        uint32_t aA  = s2u(sA)  + (uint32_t)(wm * 32 * (LDA * 4)) + aoff;
        uint32_t aB1 = s2u(sB1) + (uint32_t)(wn * 32 * (LDA * 4)) + aoff;
        uint32_t aB2 = s2u(sB2) + (uint32_t)(wn * 32 * (LDA * 4)) + aoff;
#pragma unroll
        for (int kb = 0; kb < 4; kb++) {
            uint32_t koff = kb * 32;
            uint32_t a[2][4], f1[2][4], f2[2][4];
            ldsmA(a[0], aA + koff);
            ldsmA(a[1], aA + 16 * (LDA * 4) + koff);
            ldsm4(f1[0], aB1 + koff);
            ldsm4(f1[1], aB1 + 16 * (LDA * 4) + koff);
            ldsm4(f2[0], aB2 + koff);
            ldsm4(f2[1], aB2 + 16 * (LDA * 4) + koff);
#pragma unroll
            for (int mi = 0; mi < 2; mi++)
#pragma unroll
                for (int j = 0; j < 2; j++) {
                    mma_tf32(cH[mi][2 * j],     a[mi], &f1[j][0]);
                    mma_tf32(cH[mi][2 * j + 1], a[mi], &f1[j][2]);
                    mma_tf32(cS[mi][2 * j],     a[mi], &f2[j][0]);
                    mma_tf32(cS[mi][2 * j + 1], a[mi], &f2[j][2]);
                }
        }
        __syncthreads();
    }

    // epilogue: exact GELU gate, tf32-rounded fp32 store
#pragma unroll
    for (int mi = 0; mi < 2; mi++) {
#pragma unroll
        for (int ni = 0; ni < 4; ni++) {
            int col = n0 + wn * 32 + ni * 8 + t4 * 2;
            float bi0 = bin[e * F_DIM + col], bi1 = bin[e * F_DIM + col + 1];
            float bs0 = bsc[e * F_DIM + col], bs1 = bsc[e * F_DIM + col + 1];
#pragma unroll
            for (int h = 0; h < 2; h++) {
                int row = row0 + wm * 32 + mi * 16 + g4 + h * 8;
                float h0 = cH[mi][ni][h * 2 + 0] + bi0;
                float h1 = cH[mi][ni][h * 2 + 1] + bi1;
                float s0 = cS[mi][ni][h * 2 + 0] + bs0;
                float s1 = cS[mi][ni][h * 2 + 1] + bs1;
                float gl0 = 0.5f * h0 * (1.f + erff(h0 * 0.70710678118654752f));
                float gl1 = 0.5f * h1 * (1.f + erff(h1 * 0.70710678118654752f));
                float2 o;
                o.x = __uint_as_float(f2tf(gl0 * s0));
                o.y = __uint_as_float(f2tf(gl1 * s1));
                *(float2*)(g_inner + (size_t)row * F_DIM + col) = o;
            }
        }
    }
}

// ---------------------------------------------------------------------------
// GEMM2: y = inner @ W_out + b_out; out[token] += gate * y (atomic)
// Grid (D/64, MAXTILES)
// ---------------------------------------------------------------------------
__global__ __launch_bounds__(256, 1)
void gemm2_kernel(const float* __restrict__ Wout, const float* __restrict__ bout,
                  float* __restrict__ out) {
    int e = g_tile_e[blockIdx.y];
    if (e < 0) return;
    int row0 = blockIdx.y * 128;
    int n0   = blockIdx.x * 64;

    int tid = threadIdx.x;
    int lane = tid & 31, warp = tid >> 5;
    int wm = warp & 3, wn = warp >> 2;
    int g4 = lane >> 2, t4 = lane & 3;

    int rA = tid >> 3, kv = tid & 7;
    const float* aptr[4];
#pragma unroll
    for (int i = 0; i < 4; i++)
        aptr[i] = g_inner + (size_t)(row0 + rA + i * 32) * F_DIM + kv * 4;

    int aq = lane >> 2, bq = lane & 3;
    int khB = (warp & 3) * 8;
    int nhB = (warp >> 2) * 32;
    const float* bbase = Wout + ((size_t)e * F_DIM + khB + bq) * D_DIM + n0 + nhB + aq * 4;

    uint32_t aoff = (uint32_t)(((lane & 7) + ((lane >> 4) & 1) * 8) * (LDA * 4)
                               + ((lane >> 3) & 1) * 16);

    float c[2][4][4];
#pragma unroll
    for (int mi = 0; mi < 2; mi++)
#pragma unroll
        for (int ni = 0; ni < 4; ni++)
#pragma unroll
            for (int j = 0; j < 4; j++) c[mi][ni][j] = 0.f;

    float4 av[4], bv[2];
#pragma unroll
    for (int i = 0; i < 4; i++) av[i] = *(const float4*)(aptr[i]);
#pragma unroll
    for (int p = 0; p < 2; p++)
        bv[p] = *(const float4*)(bbase + (size_t)(p * 4) * D_DIM);

    for (int it = 0; it < NS2; it++) {
        char* sA = dynsmem + (it & 1) * STAGE2;
        char* sB = sA + A_BYTES;
#pragma unroll
        for (int i = 0; i < 4; i++) {
            // g_inner already tf32-rounded: raw bit copy
            uint4 u = make_uint4(__float_as_uint(av[i].x), __float_as_uint(av[i].y),
                                 __float_as_uint(av[i].z), __float_as_uint(av[i].w));
            *(uint4*)(sA + (rA + i * 32) * (LDA * 4) + kv * 16) = u;
        }
        {
            float4 b2[4];
            b2[0] = bv[0]; b2[1] = bv[1];
            sts_B(sB, b2, 2, nhB, khB, lane);
        }
        __syncthreads();
        if (it + 1 < NS2) {
            int k0 = (it + 1) * 32;
#pragma unroll
            for (int i = 0; i < 4; i++) av[i] = *(const float4*)(aptr[i] + k0);
#pragma unroll
            for (int p = 0; p < 2; p++)
                bv[p] = *(const float4*)(bbase + (size_t)(k0 + p * 4) * D_DIM);
        }
        uint32_t aA = s2u(sA) + (uint32_t)(wm * 32 * (LDA * 4)) + aoff;
        uint32_t aB = s2u(sB) + (uint32_t)(wn * 32 * (LDA * 4)) + aoff;
#pragma unroll
        for (int kb = 0; kb < 4; kb++) {
            uint32_t koff = kb * 32;
            uint32_t a[2][4], f[2][4];
            ldsmA(a[0], aA + koff);
            ldsmA(a[1], aA + 16 * (LDA * 4) + koff);
            ldsm4(f[0], aB + koff);
            ldsm4(f[1], aB + 16 * (LDA * 4) + koff);
#pragma unroll
            for (int mi = 0; mi < 2; mi++)
#pragma unroll
                for (int j = 0; j < 2; j++) {
                    mma_tf32(c[mi][2 * j],     a[mi], &f[j][0]);
                    mma_tf32(c[mi][2 * j + 1], a[mi], &f[j][2]);
                }
        }
        __syncthreads();
    }

    // epilogue: gate-weighted atomic accumulate
#pragma unroll
    for (int mi = 0; mi < 2; mi++) {
#pragma unroll
        for (int ni = 0; ni < 4; ni++) {
            int col = n0 + wn * 32 + ni * 8 + t4 * 2;
            float b0 = bout[e * D_DIM + col], b1 = bout[e * D_DIM + col + 1];
#pragma unroll
            for (int h = 0; h < 2; h++) {
                int rowp = row0 + wm * 32 + mi * 16 + g4 + h * 8;
                int tok = g_pair_token[rowp];
                if (tok >= 0) {
                    float w = g_pair_w[rowp];
                    atomicAdd(&out[(size_t)tok * D_DIM + col],     w * (c[mi][ni][h * 2 + 0] + b0));
                    atomicAdd(&out[(size_t)tok * D_DIM + col + 1], w * (c[mi][ni][h * 2 + 1] + b1));
                }
            }
        }
    }
}

// ---------------------------------------------------------------------------
extern "C" void kernel_launch(void* const* d_in, const int* in_sizes, int n_in,
                              void* d_out, int out_size) {
    const float* states = (const float*)d_in[0];
    const float* Wg     = (const float*)d_in[1];
    const float* Win    = (const float*)d_in[2];
    const float* bin    = (const float*)d_in[3];
    const float* Wsc    = (const float*)d_in[4];
    const float* bsc    = (const float*)d_in[5];
    const float* Wout   = (const float*)d_in[6];
    const float* bout   = (const float*)d_in[7];
    float* out = (float*)d_out;

    static bool attr_set = false;
    if (!attr_set) {
        cudaFuncSetAttribute(gemm1_kernel, cudaFuncAttributeMaxDynamicSharedMemorySize, SMEM1);
        cudaFuncSetAttribute(gemm2_kernel, cudaFuncAttributeMaxDynamicSharedMemorySize, SMEM2);
        attr_set = true;
    }

    init_kernel<<<(out_size + 255) / 256, 256>>>(out, out_size);
    router_kernel<<<N_TOK / 8, 256>>>(states, Wg);
    setup_kernel<<<1, 32>>>();
    scatter_kernel<<<(NPAIR + 255) / 256, 256>>>();
    gemm1_kernel<<<dim3(F_DIM / 64, MAXTILES), 256, SMEM1>>>(states, Win, bin, Wsc, bsc);
    gemm2_kernel<<<dim3(D_DIM / 64, MAXTILES), 256, SMEM2>>>(Wout, bout, out);
}

// round 9
// speedup vs baseline: 1.0008x; 1.0008x over previous
#include <cuda_runtime.h>
#include <cuda_bf16.h>
#include <math.h>
#include <stdint.h>

// Problem constants (fixed by the dataset)
#define D_DIM   1024
#define F_DIM   2048
#define E_NUM   8
#define N_TOK   2048
#define NPAIR   4096
#define PADROWS 5120
#define MAXTILES 40
#define NS1 32            // 1024/32 K-stages, GEMM1
#define NS2 64            // 2048/32 K-stages, GEMM2
#define LDA 36            // fp32 elems per row (32 + 4 pad) -> 144B stride

#define A_BYTES  (128 * LDA * 4)          // 18432
#define B_BYTES  (64 * LDA * 4)           // 9216
#define STAGE1   (A_BYTES + 2 * B_BYTES)  // 36864
#define STAGE2   (A_BYTES + B_BYTES)      // 27648
#define SMEM1    (2 * STAGE1)             // 73728
#define SMEM2    (2 * STAGE2)             // 55296

// Scratch (device globals — no runtime allocation allowed)
__device__ float g_inner[(size_t)PADROWS * F_DIM];   // tf32-rounded fp32
__device__ int   g_pair_token[PADROWS];
__device__ float g_pair_w[PADROWS];
__device__ int   g_topi[N_TOK * 2];
__device__ float g_topw[N_TOK * 2];
__device__ int   g_counts[E_NUM];
__device__ int   g_cursor[E_NUM];
__device__ int   g_tile_e[MAXTILES];

__device__ __forceinline__ uint32_t f2tf(float f) {
    uint32_t u;
    asm("cvt.rna.tf32.f32 %0, %1;" : "=r"(u) : "f"(f));
    return u;
}
__device__ __forceinline__ uint32_t s2u(const void* p) {
    return (uint32_t)__cvta_generic_to_shared((void*)p);
}
__device__ __forceinline__ void mma_tf32(float c[4], const uint32_t a[4],
                                         const uint32_t b[2]) {
    asm volatile(
        "mma.sync.aligned.m16n8k8.row.col.f32.tf32.tf32.f32 "
        "{%0,%1,%2,%3}, {%4,%5,%6,%7}, {%8,%9}, {%0,%1,%2,%3};\n"
        : "+f"(c[0]), "+f"(c[1]), "+f"(c[2]), "+f"(c[3])
        : "r"(a[0]), "r"(a[1]), "r"(a[2]), "r"(a[3]), "r"(b[0]), "r"(b[1]));
}
__device__ __forceinline__ void ldsm4(uint32_t r[4], uint32_t addr) {
    asm volatile("ldmatrix.sync.aligned.m8n8.x4.shared.b16 {%0,%1,%2,%3}, [%4];"
                 : "=r"(r[0]), "=r"(r[1]), "=r"(r[2]), "=r"(r[3]) : "r"(addr));
}
// ldsm4 with our aoff returns {(r0-7,k0-3),(r0-7,k4-7),(r8-15,k0-3),(r8-15,k4-7)}.
// The tf32 A fragment wants {a0,a1,a2,a3}={(g4,t4),(g4+8,t4),(g4,t4+4),(g4+8,t4+4)}
// = {r0, r2, r1, r3}  -> reorder here.
__device__ __forceinline__ void ldsmA(uint32_t a[4], uint32_t addr) {
    uint32_t r[4];
    ldsm4(r, addr);
    a[0] = r[0]; a[1] = r[2]; a[2] = r[1]; a[3] = r[3];
}

// ---------------------------------------------------------------------------
// small kernels
// ---------------------------------------------------------------------------
__global__ void init_kernel(float* out, int out_size) {
    int idx = blockIdx.x * blockDim.x + threadIdx.x;
    if (idx < out_size) out[idx] = 0.f;
    if (idx < PADROWS)  g_pair_token[idx] = -1;
    if (idx < E_NUM)    g_counts[idx] = 0;
}

__global__ void router_kernel(const float* __restrict__ x,
                              const float* __restrict__ Wg) {
    int warp = threadIdx.x >> 5;
    int lane = threadIdx.x & 31;
    int n = blockIdx.x * 8 + warp;
    if (n >= N_TOK) return;
    float acc[E_NUM];
#pragma unroll
    for (int e = 0; e < E_NUM; e++) acc[e] = 0.f;
    const float* xr = x + (size_t)n * D_DIM;
    for (int d = lane; d < D_DIM; d += 32) {
        float xv = xr[d];
#pragma unroll
        for (int e = 0; e < E_NUM; e++) acc[e] += xv * Wg[d * E_NUM + e];
    }
#pragma unroll
    for (int e = 0; e < E_NUM; e++) {
#pragma unroll
        for (int off = 16; off > 0; off >>= 1)
            acc[e] += __shfl_xor_sync(0xffffffffu, acc[e], off);
    }
    if (lane == 0) {
        float m = acc[0];
#pragma unroll
        for (int e = 1; e < E_NUM; e++) m = fmaxf(m, acc[e]);
        float p[E_NUM];
#pragma unroll
        for (int e = 0; e < E_NUM; e++) p[e] = expf(acc[e] - m);
        int i1 = 0;
#pragma unroll
        for (int e = 1; e < E_NUM; e++) if (p[e] > p[i1]) i1 = e;
        int i2 = (i1 == 0) ? 1 : 0;
#pragma unroll
        for (int e = 0; e < E_NUM; e++)
            if (e != i1 && p[e] > p[i2]) i2 = e;
        float inv = 1.f / (p[i1] + p[i2]);
        g_topi[n * 2 + 0] = i1;  g_topw[n * 2 + 0] = p[i1] * inv;
        g_topi[n * 2 + 1] = i2;  g_topw[n * 2 + 1] = p[i2] * inv;
        atomicAdd(&g_counts[i1], 1);
        atomicAdd(&g_counts[i2], 1);
    }
}

__global__ void setup_kernel() {
    if (threadIdx.x != 0 || blockIdx.x != 0) return;
    int off = 0;
    int pad[E_NUM];
    for (int e = 0; e < E_NUM; e++) {
        g_cursor[e] = off;
        int p = ((g_counts[e] + 127) / 128) * 128;
        pad[e] = p;
        off += p;
    }
    int t = 0;
    for (int e = 0; e < E_NUM; e++)
        for (int r = 0; r < pad[e]; r += 128) g_tile_e[t++] = e;
    for (; t < MAXTILES; t++) g_tile_e[t] = -1;
}

__global__ void scatter_kernel() {
    int idx = blockIdx.x * blockDim.x + threadIdx.x;
    if (idx >= NPAIR) return;
    int e = g_topi[idx];
    int pos = atomicAdd(&g_cursor[e], 1);
    g_pair_token[pos] = idx >> 1;
    g_pair_w[pos] = g_topw[idx];
}

// ---------------------------------------------------------------------------
// B-tile store: cvt.rna + 4x4 shfl transpose + STS.128 (conflict-free).
// Lane (a = lane>>2, b = lane&3) loaded bv[p] = W[khb+4p+b][n cols nh+a*4..+3].
// After transpose lane holds n = nh + a*4 + b, k-run of 4 at khb+4p.
// ---------------------------------------------------------------------------
__device__ __forceinline__ void sts_B(char* sB, const float4* bv, int np,
                                      int nh, int khb, int lane) {
    int a = lane >> 2, b = lane & 3;
#pragma unroll
    for (int p = 0; p < 4; p++) {
        if (p >= np) break;
        uint32_t t[4] = { f2tf(bv[p].x), f2tf(bv[p].y), f2tf(bv[p].z), f2tf(bv[p].w) };
        uint32_t w4[4];
#pragma unroll
        for (int s = 0; s < 4; s++) {
            int j = (b - s) & 3;
            w4[j] = __shfl_sync(0xffffffffu, t[(b + s) & 3], (lane & ~3) | j);
        }
        int n = nh + a * 4 + b;
        *(uint4*)(sB + n * (LDA * 4) + (khb + p * 4) * 4) =
            make_uint4(w4[0], w4[1], w4[2], w4[3]);
    }
}

// ---------------------------------------------------------------------------
// GEMM1: inner = gelu(X@W_in + b_in) * (X@W_scale + b_scale)
// Grid (F/64, MAXTILES). 256 thr, warps: wm=warp&3 (32 rows), wn=warp>>2 (32 cols).
// ---------------------------------------------------------------------------
extern __shared__ __align__(16) char dynsmem[];

__global__ __launch_bounds__(256, 1)
void gemm1_kernel(const float* __restrict__ x,   const float* __restrict__ Win,
                  const float* __restrict__ bin, const float* __restrict__ Wsc,
                  const float* __restrict__ bsc) {
    int e = g_tile_e[blockIdx.y];
    if (e < 0) return;
    int row0 = blockIdx.y * 128;
    int n0   = blockIdx.x * 64;

    int tid = threadIdx.x;
    int lane = tid & 31, warp = tid >> 5;
    int wm = warp & 3, wn = warp >> 2;
    int g4 = lane >> 2, t4 = lane & 3;

    // A gather mapping: rows rA + 32i, fixed kv
    int rA = tid >> 3, kv = tid & 7;
    const float* xptr[4];
    bool tval[4];
#pragma unroll
    for (int i = 0; i < 4; i++) {
        int tok = g_pair_token[row0 + rA + i * 32];
        tval[i] = (tok >= 0);
        xptr[i] = x + (size_t)(tok >= 0 ? tok : 0) * D_DIM + kv * 4;
    }
    // B loader mapping: warp -> matrix (warp&1), k-half khB, n-half nhB
    int aq = lane >> 2, bq = lane & 3;
    int khB = ((warp >> 1) & 1) * 16;
    int nhB = (warp >> 2) * 32;
    const float* wsel = (warp & 1) ? Wsc : Win;
    const float* bbase = wsel + ((size_t)e * D_DIM + khB + bq) * F_DIM + n0 + nhB + aq * 4;

    // ldmatrix per-lane offset: lanes 0-7 rows 0-7 k0-3; 8-15 rows 0-7 k4-7;
    // 16-23 rows 8-15 k0-3; 24-31 rows 8-15 k4-7.
    uint32_t aoff = (uint32_t)(((lane & 7) + ((lane >> 4) & 1) * 8) * (LDA * 4)
                               + ((lane >> 3) & 1) * 16);

    float cH[2][4][4], cS[2][4][4];
#pragma unroll
    for (int mi = 0; mi < 2; mi++)
#pragma unroll
        for (int ni = 0; ni < 4; ni++)
#pragma unroll
            for (int j = 0; j < 4; j++) { cH[mi][ni][j] = 0.f; cS[mi][ni][j] = 0.f; }

    float4 av[4], bv[4];
    // prologue loads for k0 = 0
#pragma unroll
    for (int i = 0; i < 4; i++)
        av[i] = tval[i] ? *(const float4*)(xptr[i]) : make_float4(0.f, 0.f, 0.f, 0.f);
#pragma unroll
    for (int p = 0; p < 4; p++)
        bv[p] = *(const float4*)(bbase + (size_t)(p * 4) * F_DIM);

    for (int it = 0; it < NS1; it++) {
        char* sA  = dynsmem + (it & 1) * STAGE1;
        char* sB1 = sA + A_BYTES;
        char* sB2 = sB1 + B_BYTES;
        // store current stage
#pragma unroll
        for (int i = 0; i < 4; i++) {
            uint4 u = make_uint4(f2tf(av[i].x), f2tf(av[i].y), f2tf(av[i].z), f2tf(av[i].w));
            *(uint4*)(sA + (rA + i * 32) * (LDA * 4) + kv * 16) = u;
        }
        sts_B((warp & 1) ? sB2 : sB1, bv, 4, nhB, khB, lane);
        __syncthreads();
        // prefetch next stage
        if (it + 1 < NS1) {
            int k0 = (it + 1) * 32;
#pragma unroll
            for (int i = 0; i < 4; i++)
                av[i] = tval[i] ? *(const float4*)(xptr[i] + k0)
                                : make_float4(0.f, 0.f, 0.f, 0.f);
#pragma unroll
            for (int p = 0; p < 4; p++)
                bv[p] = *(const float4*)(bbase + (size_t)(k0 + p * 4) * F_DIM);
        }
        // compute
        uint32_t aA  = s2u(sA)  + (uint32_t)(wm * 32 * (LDA * 4)) + aoff;
        uint32_t aB1 = s2u(sB1) + (uint32_t)(wn * 32 * (LDA * 4)) + aoff;
        uint32_t aB2 = s2u(sB2) + (uint32_t)(wn * 32 * (LDA * 4)) + aoff;
#pragma unroll
        for (int kb = 0; kb < 4; kb++) {
            uint32_t koff = kb * 32;
            uint32_t a[2][4], f1[2][4], f2[2][4];
            ldsmA(a[0], aA + koff);
            ldsmA(a[1], aA + 16 * (LDA * 4) + koff);
            ldsm4(f1[0], aB1 + koff);
            ldsm4(f1[1], aB1 + 16 * (LDA * 4) + koff);
            ldsm4(f2[0], aB2 + koff);
            ldsm4(f2[1], aB2 + 16 * (LDA * 4) + koff);
#pragma unroll
            for (int mi = 0; mi < 2; mi++)
#pragma unroll
                for (int j = 0; j < 2; j++) {
                    mma_tf32(cH[mi][2 * j],     a[mi], &f1[j][0]);
                    mma_tf32(cH[mi][2 * j + 1], a[mi], &f1[j][2]);
                    mma_tf32(cS[mi][2 * j],     a[mi], &f2[j][0]);
                    mma_tf32(cS[mi][2 * j + 1], a[mi], &f2[j][2]);
                }
        }
        __syncthreads();
    }

    // epilogue: exact GELU gate, tf32-rounded fp32 store
#pragma unroll
    for (int mi = 0; mi < 2; mi++) {
#pragma unroll
        for (int ni = 0; ni < 4; ni++) {
            int col = n0 + wn * 32 + ni * 8 + t4 * 2;
            float bi0 = bin[e * F_DIM + col], bi1 = bin[e * F_DIM + col + 1];
            float bs0 = bsc[e * F_DIM + col], bs1 = bsc[e * F_DIM + col + 1];
#pragma unroll
            for (int h = 0; h < 2; h++) {
                int row = row0 + wm * 32 + mi * 16 + g4 + h * 8;
                float h0 = cH[mi][ni][h * 2 + 0] + bi0;
                float h1 = cH[mi][ni][h * 2 + 1] + bi1;
                float s0 = cS[mi][ni][h * 2 + 0] + bs0;
                float s1 = cS[mi][ni][h * 2 + 1] + bs1;
                float gl0 = 0.5f * h0 * (1.f + erff(h0 * 0.70710678118654752f));
                float gl1 = 0.5f * h1 * (1.f + erff(h1 * 0.70710678118654752f));
                float2 o;
                o.x = __uint_as_float(f2tf(gl0 * s0));
                o.y = __uint_as_float(f2tf(gl1 * s1));
                *(float2*)(g_inner + (size_t)row * F_DIM + col) = o;
            }
        }
    }
}

// ---------------------------------------------------------------------------
// GEMM2: y = inner @ W_out + b_out; out[token] += gate * y (atomic)
// Grid (D/64, MAXTILES)
// ---------------------------------------------------------------------------
__global__ __launch_bounds__(256, 1)
void gemm2_kernel(const float* __restrict__ Wout, const float* __restrict__ bout,
                  float* __restrict__ out) {
    int e = g_tile_e[blockIdx.y];
    if (e < 0) return;
    int row0 = blockIdx.y * 128;
    int n0   = blockIdx.x * 64;

    int tid = threadIdx.x;
    int lane = tid & 31, warp = tid >> 5;
    int wm = warp & 3, wn = warp >> 2;
    int g4 = lane >> 2, t4 = lane & 3;

    int rA = tid >> 3, kv = tid & 7;
    const float* aptr[4];
#pragma unroll
    for (int i = 0; i < 4; i++)
        aptr[i] = g_inner + (size_t)(row0 + rA + i * 32) * F_DIM + kv * 4;

    int aq = lane >> 2, bq = lane & 3;
    int khB = (warp & 3) * 8;
    int nhB = (warp >> 2) * 32;
    const float* bbase = Wout + ((size_t)e * F_DIM + khB + bq) * D_DIM + n0 + nhB + aq * 4;

    uint32_t aoff = (uint32_t)(((lane & 7) + ((lane >> 4) & 1) * 8) * (LDA * 4)
                               + ((lane >> 3) & 1) * 16);

    float c[2][4][4];
#pragma unroll
    for (int mi = 0; mi < 2; mi++)
#pragma unroll
        for (int ni = 0; ni < 4; ni++)
#pragma unroll
            for (int j = 0; j < 4; j++) c[mi][ni][j] = 0.f;

    float4 av[4], bv[2];
#pragma unroll
    for (int i = 0; i < 4; i++) av[i] = *(const float4*)(aptr[i]);
#pragma unroll
    for (int p = 0; p < 2; p++)
        bv[p] = *(const float4*)(bbase + (size_t)(p * 4) * D_DIM);

    for (int it = 0; it < NS2; it++) {
        char* sA = dynsmem + (it & 1) * STAGE2;
        char* sB = sA + A_BYTES;
#pragma unroll
        for (int i = 0; i < 4; i++) {
            // g_inner already tf32-rounded: raw bit copy
            uint4 u = make_uint4(__float_as_uint(av[i].x), __float_as_uint(av[i].y),
                                 __float_as_uint(av[i].z), __float_as_uint(av[i].w));
            *(uint4*)(sA + (rA + i * 32) * (LDA * 4) + kv * 16) = u;
        }
        {
            float4 b2[4];
            b2[0] = bv[0]; b2[1] = bv[1];
            sts_B(sB, b2, 2, nhB, khB, lane);
        }
        __syncthreads();
        if (it + 1 < NS2) {
            int k0 = (it + 1) * 32;
#pragma unroll
            for (int i = 0; i < 4; i++) av[i] = *(const float4*)(aptr[i] + k0);
#pragma unroll
            for (int p = 0; p < 2; p++)
                bv[p] = *(const float4*)(bbase + (size_t)(k0 + p * 4) * D_DIM);
        }
        uint32_t aA = s2u(sA) + (uint32_t)(wm * 32 * (LDA * 4)) + aoff;
        uint32_t aB = s2u(sB) + (uint32_t)(wn * 32 * (LDA * 4)) + aoff;
#pragma unroll
        for (int kb = 0; kb < 4; kb++) {
            uint32_t koff = kb * 32;
            uint32_t a[2][4], f[2][4];
            ldsmA(a[0], aA + koff);
            ldsmA(a[1], aA + 16 * (LDA * 4) + koff);
            ldsm4(f[0], aB + koff);
            ldsm4(f[1], aB + 16 * (LDA * 4) + koff);
#pragma unroll
            for (int mi = 0; mi < 2; mi++)
#pragma unroll
                for (int j = 0; j < 2; j++) {
                    mma_tf32(c[mi][2 * j],     a[mi], &f[j][0]);
                    mma_tf32(c[mi][2 * j + 1], a[mi], &f[j][2]);
                }
        }
        __syncthreads();
    }

    // epilogue: gate-weighted atomic accumulate
#pragma unroll
    for (int mi = 0; mi < 2; mi++) {
#pragma unroll
        for (int ni = 0; ni < 4; ni++) {
            int col = n0 + wn * 32 + ni * 8 + t4 * 2;
            float b0 = bout[e * D_DIM + col], b1 = bout[e * D_DIM + col + 1];
#pragma unroll
            for (int h = 0; h < 2; h++) {
                int rowp = row0 + wm * 32 + mi * 16 + g4 + h * 8;
                int tok = g_pair_token[rowp];
                if (tok >= 0) {
                    float w = g_pair_w[rowp];
                    atomicAdd(&out[(size_t)tok * D_DIM + col],     w * (c[mi][ni][h * 2 + 0] + b0));
                    atomicAdd(&out[(size_t)tok * D_DIM + col + 1], w * (c[mi][ni][h * 2 + 1] + b1));
                }
            }
        }
    }
}

// ---------------------------------------------------------------------------
extern "C" void kernel_launch(void* const* d_in, const int* in_sizes, int n_in,
                              void* d_out, int out_size) {
    const float* states = (const float*)d_in[0];
    const float* Wg     = (const float*)d_in[1];
    const float* Win    = (const float*)d_in[2];
    const float* bin    = (const float*)d_in[3];
    const float* Wsc    = (const float*)d_in[4];
    const float* bsc    = (const float*)d_in[5];
    const float* Wout   = (const float*)d_in[6];
    const float* bout   = (const float*)d_in[7];
    float* out = (float*)d_out;

    static bool attr_set = false;
    if (!attr_set) {
        cudaFuncSetAttribute(gemm1_kernel, cudaFuncAttributeMaxDynamicSharedMemorySize, SMEM1);
        cudaFuncSetAttribute(gemm2_kernel, cudaFuncAttributeMaxDynamicSharedMemorySize, SMEM2);
        attr_set = true;
    }

    init_kernel<<<(out_size + 255) / 256, 256>>>(out, out_size);
    router_kernel<<<N_TOK / 8, 256>>>(states, Wg);
    setup_kernel<<<1, 32>>>();
    scatter_kernel<<<(NPAIR + 255) / 256, 256>>>();
    gemm1_kernel<<<dim3(F_DIM / 64, MAXTILES), 256, SMEM1>>>(states, Win, bin, Wsc, bsc);
    gemm2_kernel<<<dim3(D_DIM / 64, MAXTILES), 256, SMEM2>>>(Wout, bout, out);
}